// round 1
// baseline (speedup 1.0000x reference)
#include <cuda_runtime.h>

// Shapes (fixed by the problem): b=4, c=256, H=W=64 -> n=4096, k=c/8=32
#define BB   4
#define CCH  256
#define NN   4096
#define KD   32
#define RTOT 320   // 32 (f) + 32 (g) + 256 (h) weight rows

// Scratch (device globals -- no cudaMalloc allowed)
__device__ float g_K[BB * NN * KD];   // f^T : keys    [b][n][32]
__device__ float g_Q[BB * NN * KD];   // g^T : queries [b][n][32]
__device__ float g_V[BB * NN * CCH];  // h^T : values  [b][n][256]

// ---------------------------------------------------------------------------
// Kernel 1: projections. Out(320, n) = W(320,256) @ X(256, n) per batch,
// written transposed into g_K / g_Q / g_V with coalesced stores.
// Block: 256 threads, tile = 64 pixels. Channel-chunked (64) weight staging.
// ---------------------------------------------------------------------------
struct ProjSmem {
    union {
        struct {
            float xc[64][68];     // X chunk: 64 channels x 64 pixels (padded)
            float wc[RTOT][68];   // W chunk: 320 rows x 64 channels (padded)
        } a;
        float ot[64][324];        // output staging: [pixel][row], padded
    };
};

__global__ __launch_bounds__(256, 2)
void proj_kernel(const float* __restrict__ t_in,
                 const float* __restrict__ f_w, const float* __restrict__ f_b,
                 const float* __restrict__ g_w, const float* __restrict__ g_b,
                 const float* __restrict__ h_w, const float* __restrict__ h_b)
{
    extern __shared__ char smem_raw[];
    ProjSmem& sm = *reinterpret_cast<ProjSmem*>(smem_raw);

    const int tid = threadIdx.x;
    const int b   = blockIdx.y;
    const int n0  = blockIdx.x * 64;
    const int typ = tid >> 3;  // 0..31 : row group
    const int txp = tid & 7;   // 0..7  : pixel group (8 pixels each)

    float acc[10][8];
#pragma unroll
    for (int k = 0; k < 10; ++k)
#pragma unroll
        for (int i = 0; i < 8; ++i) acc[k][i] = 0.f;

    for (int cc = 0; cc < CCH; cc += 64) {
        __syncthreads();
        // Load X chunk: 64 channels x 64 pixels (coalesced float4)
        for (int idx = tid; idx < 64 * 16; idx += 256) {
            int c = idx >> 4, p4 = idx & 15;
            float4 v = *reinterpret_cast<const float4*>(
                t_in + (b * CCH + cc + c) * NN + n0 + p4 * 4);
            *reinterpret_cast<float4*>(&sm.a.xc[c][p4 * 4]) = v;
        }
        // Load W chunk: 320 rows x 64 channels
        for (int idx = tid; idx < RTOT * 16; idx += 256) {
            int r = idx >> 4, c4 = idx & 15;
            const float* wrow = (r < 32) ? (f_w + r * CCH)
                              : (r < 64) ? (g_w + (r - 32) * CCH)
                                         : (h_w + (r - 64) * CCH);
            float4 v = *reinterpret_cast<const float4*>(wrow + cc + c4 * 4);
            *reinterpret_cast<float4*>(&sm.a.wc[r][c4 * 4]) = v;
        }
        __syncthreads();

#pragma unroll 4
        for (int c = 0; c < 64; ++c) {
            float4 x0 = *reinterpret_cast<float4*>(&sm.a.xc[c][txp * 8]);
            float4 x1 = *reinterpret_cast<float4*>(&sm.a.xc[c][txp * 8 + 4]);
            float xv[8] = {x0.x, x0.y, x0.z, x0.w, x1.x, x1.y, x1.z, x1.w};
#pragma unroll
            for (int k = 0; k < 10; ++k) {
                float wv = sm.a.wc[typ + 32 * k][c];
#pragma unroll
                for (int i = 0; i < 8; ++i) acc[k][i] += wv * xv[i];
            }
        }
    }

    // Bias
#pragma unroll
    for (int k = 0; k < 10; ++k) {
        int r = typ + 32 * k;
        float bv = (r < 32) ? f_b[r] : (r < 64) ? g_b[r - 32] : h_b[r - 64];
#pragma unroll
        for (int i = 0; i < 8; ++i) acc[k][i] += bv;
    }

    // Stage transposed: ot[pixel][row]
    __syncthreads();
#pragma unroll
    for (int k = 0; k < 10; ++k)
#pragma unroll
        for (int i = 0; i < 8; ++i)
            sm.ot[txp * 8 + i][typ + 32 * k] = acc[k][i];
    __syncthreads();

    // Coalesced stores to scratch
    // V: rows 64..319 -> g_V[b][n][256]
    for (int idx = tid; idx < 64 * 64; idx += 256) {
        int p = idx >> 6, c4 = idx & 63;
        float4 v = *reinterpret_cast<float4*>(&sm.ot[p][64 + c4 * 4]);
        *reinterpret_cast<float4*>(g_V + ((b * NN) + n0 + p) * CCH + c4 * 4) = v;
    }
    // K: rows 0..31 -> g_K[b][n][32]
    for (int idx = tid; idx < 64 * 8; idx += 256) {
        int p = idx >> 3, r4 = idx & 7;
        float4 v = *reinterpret_cast<float4*>(&sm.ot[p][r4 * 4]);
        *reinterpret_cast<float4*>(g_K + ((b * NN) + n0 + p) * KD + r4 * 4) = v;
    }
    // Q: rows 32..63 -> g_Q[b][n][32]
    for (int idx = tid; idx < 64 * 8; idx += 256) {
        int p = idx >> 3, r4 = idx & 7;
        float4 v = *reinterpret_cast<float4*>(&sm.ot[p][32 + r4 * 4]);
        *reinterpret_cast<float4*>(g_Q + ((b * NN) + n0 + p) * KD + r4 * 4) = v;
    }
}

// ---------------------------------------------------------------------------
// Kernel 2: flash attention + fused epilogue.
// Block = 64 queries x 256 channels; key tiles of 64; online softmax.
// Thread (warp w, lane l): queries {w, w+8, ..., w+56}, channels l*8..l*8+7.
// ---------------------------------------------------------------------------
struct AttnSmem {
    float q[64][33];
    float k[64][33];
    float v[64][256];
    float s[64][65];   // S, then P; reused as output transpose buffer
    float m[64];
    float l[64];
    float al[64];
};

__global__ __launch_bounds__(256, 2)
void attn_kernel(const float* __restrict__ t_in,
                 const float* __restrict__ gamma,
                 float* __restrict__ out)
{
    extern __shared__ char smem_raw[];
    AttnSmem& sm = *reinterpret_cast<AttnSmem*>(smem_raw);

    const int tid  = threadIdx.x;
    const int b    = blockIdx.y;
    const int n0   = blockIdx.x * 64;     // query tile base
    const int lane = tid & 31;
    const int wid  = tid >> 5;            // 0..7
    const int c0   = lane * 8;            // channel base for PV

    // Load Q tile (once)
    for (int idx = tid; idx < 64 * 32; idx += 256) {
        int q = idx >> 5, d = idx & 31;
        sm.q[q][d] = g_Q[((b * NN) + n0 + q) * KD + d];
    }
    if (tid < 64) { sm.m[tid] = -1e30f; sm.l[tid] = 0.f; }

    float acc[8][8];
#pragma unroll
    for (int k = 0; k < 8; ++k)
#pragma unroll
        for (int i = 0; i < 8; ++i) acc[k][i] = 0.f;

    for (int kt = 0; kt < NN / 64; ++kt) {
        const int kk0 = kt * 64;
        __syncthreads();   // previous tile's smem fully consumed
        // Load K tile
        for (int idx = tid; idx < 64 * 32; idx += 256) {
            int r = idx >> 5, d = idx & 31;
            sm.k[r][d] = g_K[((b * NN) + kk0 + r) * KD + d];
        }
        // Load V tile
        for (int idx = tid; idx < 64 * 64; idx += 256) {
            int r = idx >> 6, c4 = idx & 63;
            *reinterpret_cast<float4*>(&sm.v[r][c4 * 4]) =
                *reinterpret_cast<const float4*>(
                    g_V + ((b * NN) + kk0 + r) * CCH + c4 * 4);
        }
        __syncthreads();

        // S = Q @ K^T : warp wid -> queries wid*8..+7 ; lane -> keys 2*lane,2*lane+1
        {
            float sacc[8][2];
#pragma unroll
            for (int qq = 0; qq < 8; ++qq) { sacc[qq][0] = 0.f; sacc[qq][1] = 0.f; }
#pragma unroll 4
            for (int d = 0; d < 32; ++d) {
                float k0 = sm.k[lane * 2][d];
                float k1 = sm.k[lane * 2 + 1][d];
#pragma unroll
                for (int qq = 0; qq < 8; ++qq) {
                    float qv = sm.q[wid * 8 + qq][d];
                    sacc[qq][0] += qv * k0;
                    sacc[qq][1] += qv * k1;
                }
            }
#pragma unroll
            for (int qq = 0; qq < 8; ++qq) {
                sm.s[wid * 8 + qq][lane * 2]     = sacc[qq][0];
                sm.s[wid * 8 + qq][lane * 2 + 1] = sacc[qq][1];
            }
        }
        __syncthreads();

        // Online softmax bookkeeping: one thread per query row
        if (tid < 64) {
            float mold = sm.m[tid];
            float tmax = mold;
            for (int j = 0; j < 64; ++j) tmax = fmaxf(tmax, sm.s[tid][j]);
            float alpha = __expf(mold - tmax);
            float psum = 0.f;
            for (int j = 0; j < 64; ++j) {
                float p = __expf(sm.s[tid][j] - tmax);
                sm.s[tid][j] = p;
                psum += p;
            }
            sm.m[tid]  = tmax;
            sm.l[tid]  = sm.l[tid] * alpha + psum;
            sm.al[tid] = alpha;
        }
        __syncthreads();

        // Rescale accumulators, then PV: acc += P @ V
#pragma unroll
        for (int k = 0; k < 8; ++k) {
            float a = sm.al[wid + 8 * k];
#pragma unroll
            for (int i = 0; i < 8; ++i) acc[k][i] *= a;
        }
#pragma unroll 2
        for (int kj = 0; kj < 64; ++kj) {
            float4 v0 = *reinterpret_cast<float4*>(&sm.v[kj][c0]);
            float4 v1 = *reinterpret_cast<float4*>(&sm.v[kj][c0 + 4]);
            float vv[8] = {v0.x, v0.y, v0.z, v0.w, v1.x, v1.y, v1.z, v1.w};
#pragma unroll
            for (int k = 0; k < 8; ++k) {
                float p = sm.s[wid + 8 * k][kj];
#pragma unroll
                for (int i = 0; i < 8; ++i) acc[k][i] += p * vv[i];
            }
        }
    }

    // Finalize: divide by l, scale by gamma, add residual; transpose via smem
    const float gam = gamma[0];
#pragma unroll
    for (int k = 0; k < 8; ++k) {
        float linv = 1.f / sm.l[wid + 8 * k];
#pragma unroll
        for (int i = 0; i < 8; ++i) acc[k][i] *= linv;
    }

    const int cgrp    = lane >> 3;          // which 64-channel chunk I own
    const int c_local = tid >> 2;           // 0..63 (writer mapping)
    const int q_base  = (tid & 3) * 16;

    for (int cc = 0; cc < 4; ++cc) {
        __syncthreads();
        if (cgrp == cc) {
#pragma unroll
            for (int k = 0; k < 8; ++k)
#pragma unroll
                for (int i = 0; i < 8; ++i)
                    sm.s[wid + 8 * k][(lane & 7) * 8 + i] = acc[k][i];
        }
        __syncthreads();
        int c = cc * 64 + c_local;
        int base = (b * CCH + c) * NN + n0;
#pragma unroll
        for (int t = 0; t < 4; ++t) {
            int q = q_base + t * 4;
            float4 ti = *reinterpret_cast<const float4*>(t_in + base + q);
            float4 o;
            o.x = gam * sm.s[q + 0][c_local] + ti.x;
            o.y = gam * sm.s[q + 1][c_local] + ti.y;
            o.z = gam * sm.s[q + 2][c_local] + ti.z;
            o.w = gam * sm.s[q + 3][c_local] + ti.w;
            *reinterpret_cast<float4*>(out + base + q) = o;
        }
    }
}

// ---------------------------------------------------------------------------
extern "C" void kernel_launch(void* const* d_in, const int* in_sizes, int n_in,
                              void* d_out, int out_size)
{
    const float* t_in  = (const float*)d_in[0];
    const float* f_w   = (const float*)d_in[1];
    const float* f_b   = (const float*)d_in[2];
    const float* g_w   = (const float*)d_in[3];
    const float* g_b   = (const float*)d_in[4];
    const float* h_w   = (const float*)d_in[5];
    const float* h_b   = (const float*)d_in[6];
    const float* gamma = (const float*)d_in[7];
    float* out = (float*)d_out;

    const int proj_smem = (int)sizeof(ProjSmem);
    const int attn_smem = (int)sizeof(AttnSmem);
    cudaFuncSetAttribute(proj_kernel,
                         cudaFuncAttributeMaxDynamicSharedMemorySize, proj_smem);
    cudaFuncSetAttribute(attn_kernel,
                         cudaFuncAttributeMaxDynamicSharedMemorySize, attn_smem);

    dim3 grid(NN / 64, BB);
    proj_kernel<<<grid, 256, proj_smem>>>(t_in, f_w, f_b, g_w, g_b, h_w, h_b);
    attn_kernel<<<grid, 256, attn_smem>>>(t_in, gamma, out);
}